// round 11
// baseline (speedup 1.0000x reference)
#include <cuda_runtime.h>
#include <math.h>
#include <stdint.h>

// ----------------------------------------------------------------------------
// BidirectionalPropagation (BasicVSR++ style) on GB300. B=1,T=8,C=64,96x96,DG=16
// R10: conv3x3 reverted to R8 (best known). gemm_k rewritten: weights staged
//      ONCE (duplicated pairs, no in-loop barriers) + FFMA2 on the natural
//      (px0,px1)/(w,w) pairs.
// ----------------------------------------------------------------------------

#define HWP 9216          // 96*96
#define CH  (64 * HWP)

__device__ float g_fb[8][CH];
__device__ float g_ff[8][CH];
__device__ float g_hA[CH];
__device__ float g_hB[CH];
__device__ float g_out4[432 * HWP];
__device__ float g_cols[1152 * HWP];
__device__ float g_dcn[CH];

#define ROWW   40
#define CINSZ  (18 * ROWW)          // 720 floats per cin
#define SW_OFF (8 * CINSZ)          // 5760
#define NSTG   3

typedef unsigned long long u64;

__device__ __forceinline__ u64 ffma2(u64 a, u64 b, u64 c) {
    u64 d;
    asm("fma.rn.f32x2 %0, %1, %2, %3;" : "=l"(d) : "l"(a), "l"(b), "l"(c));
    return d;
}
__device__ __forceinline__ u64 pk(float lo, float hi) {
    u64 d;
    asm("mov.b64 %0, {%1, %2};" : "=l"(d) : "f"(lo), "f"(hi));
    return d;
}
__device__ __forceinline__ void upk(u64 v, float& lo, float& hi) {
    asm("mov.b64 {%0, %1}, %2;" : "=f"(lo), "=f"(hi) : "l"(v));
}

__device__ __forceinline__ void cp16(uint32_t d, const void* g, int sz) {
    asm volatile("cp.async.ca.shared.global [%0], [%1], 16, %2;\n"
                 :: "r"(d), "l"(g), "r"(sz));
}
__device__ __forceinline__ void cp4(uint32_t d, const void* g) {
    asm volatile("cp.async.ca.shared.global [%0], [%1], 4;\n"
                 :: "r"(d), "l"(g));
}
#define CP_COMMIT() asm volatile("cp.async.commit_group;\n" ::: "memory")
#define CP_WAIT1()  asm volatile("cp.async.wait_group 1;\n" ::: "memory")

// ---------------------------------------------------------------------------
// conv3x3 (R8): tile 32x16 px, 256 threads, cin-split across two warp-groups.
// Each thread: 4 consecutive px x COPB couts. grid = (18, Cout/COPB).
// ---------------------------------------------------------------------------
template <int COPB>
__global__ __launch_bounds__(256) void conv3x3_k(
    const float* __restrict__ in0, const float* __restrict__ in1,
    const float* __restrict__ in2, int cinBlocks,
    const float* __restrict__ wgt, const float* __restrict__ bias,
    const float* __restrict__ addsrc, float* __restrict__ out, int act)
{
    constexpr int WSLOTS = 8 * 9 * COPB;
    constexpr int STG_F  = SW_OFF + WSLOTS;
    constexpr int NWIT   = (WSLOTS + 255) / 256;
    constexpr int NACC   = 4 * COPB;

    extern __shared__ float smem[];
    const int tid = threadIdx.x;
    const int tX = (blockIdx.x % 3) * 32;
    const int tY = (blockIdx.x / 3) * 16;
    const int coBase = blockIdx.y * COPB;
    const int lid  = tid & 127;
    const int wg   = tid >> 7;
    const int txg  = lid & 7;
    const int ty   = lid >> 3;
    const int Cin = cinBlocks * 64;

    const float* ptrs[3] = {in0, in1, in2};
    const float* actp[3]; int actc[3]; int na = 0;
    for (int b = 0; b < cinBlocks; b++)
        if (ptrs[b]) { actp[na] = ptrs[b]; actc[na] = b * 64; na++; }
    const int nSuper = na * 8;

    int in_goff[6]; unsigned in_val = 0;
#pragma unroll
    for (int i = 0; i < 6; i++) {
        int slot = tid + i * 256;
        if (slot < 1440) {
            int c = slot / 180; int rem = slot - c * 180;
            int r = rem / 10;   int q = rem - r * 10;
            int gy = tY - 1 + r, gx = tX - 4 + q * 4;
            bool v = ((unsigned)gy < 96u) && ((unsigned)gx < 96u);
            in_goff[i] = v ? (c * HWP + gy * 96 + gx) : 0;
            if (v) in_val |= (1u << i);
        } else in_goff[i] = 0;
    }
    int w_goff[NWIT];
#pragma unroll
    for (int i = 0; i < NWIT; i++) {
        int slot = tid + i * 256;
        if (slot < WSLOTS) {
            int c = slot / (9 * COPB); int rem = slot - c * (9 * COPB);
            int k9 = rem / COPB;       int co = rem - k9 * COPB;
            w_goff[i] = ((coBase + co) * Cin + c) * 9 + k9;
        } else w_goff[i] = 0;
    }

    const uint32_t s32 = (uint32_t)__cvta_generic_to_shared(smem);

    auto PREFETCH = [&](int sb, int stg) {
        const float* base = actp[sb >> 3] + ((sb & 7) * 8) * HWP;
        const uint32_t d0 = s32 + (uint32_t)stg * (STG_F * 4) + tid * 16;
#pragma unroll
        for (int i = 0; i < 5; i++)
            cp16(d0 + i * 4096, base + in_goff[i], ((in_val >> i) & 1) ? 16 : 0);
        if (tid < 160)
            cp16(d0 + 5 * 4096, base + in_goff[5], ((in_val >> 5) & 1) ? 16 : 0);
        const float* wbase = wgt + (actc[sb >> 3] + (sb & 7) * 8) * 9;
        const uint32_t w0 = s32 + (uint32_t)stg * (STG_F * 4) + SW_OFF * 4 + tid * 4;
#pragma unroll
        for (int i = 0; i < NWIT; i++) {
            if (tid + i * 256 < WSLOTS)
                cp4(w0 + i * 1024, wbase + w_goff[i]);
        }
    };

    float acc[NACC];
#pragma unroll
    for (int i = 0; i < NACC; i++) acc[i] = 0.f;

    PREFETCH(0, 0); CP_COMMIT();
    PREFETCH(1, 1); CP_COMMIT();

    int stg = 0, pstg = 2;
    for (int s = 0; s < nSuper; s++) {
        CP_WAIT1();
        __syncthreads();
        const float* st = smem + stg * STG_F;

#pragma unroll
        for (int cc8 = 0; cc8 < 4; cc8++) {
            const int c = wg * 4 + cc8;
            const float* sp = st + c * CINSZ + ty * ROWW + txg * 4;
            float iv[18];
#pragma unroll
            for (int r = 0; r < 3; r++) {
                const float4 m = *(const float4*)(sp + r * ROWW + 4);
                iv[r * 6 + 0] = sp[r * ROWW + 3];
                iv[r * 6 + 1] = m.x; iv[r * 6 + 2] = m.y;
                iv[r * 6 + 3] = m.z; iv[r * 6 + 4] = m.w;
                iv[r * 6 + 5] = sp[r * ROWW + 8];
            }
            const float* wp = st + SW_OFF + c * (9 * COPB);
#pragma unroll
            for (int k9 = 0; k9 < 9; k9++) {
                const int r = k9 / 3, ccc = k9 - r * 3;
#pragma unroll
                for (int cg = 0; cg < COPB / 4; cg++) {
                    const float4 wv = *(const float4*)(wp + k9 * COPB + cg * 4);
#pragma unroll
                    for (int j = 0; j < 4; j++) {
                        const float x = iv[r * 6 + ccc + j];
                        acc[cg * 16 + 0  + j] = fmaf(x, wv.x, acc[cg * 16 + 0  + j]);
                        acc[cg * 16 + 4  + j] = fmaf(x, wv.y, acc[cg * 16 + 4  + j]);
                        acc[cg * 16 + 8  + j] = fmaf(x, wv.z, acc[cg * 16 + 8  + j]);
                        acc[cg * 16 + 12 + j] = fmaf(x, wv.w, acc[cg * 16 + 12 + j]);
                    }
                }
            }
        }

        if (s + 2 < nSuper) PREFETCH(s + 2, pstg);
        CP_COMMIT();
        stg = (stg == 2) ? 0 : stg + 1;
        pstg = (pstg == 2) ? 0 : pstg + 1;
    }

    __syncthreads();
    if (wg == 1) {
#pragma unroll
        for (int i = 0; i < NACC; i++)
            smem[i * 128 + lid] = acc[i];
    }
    __syncthreads();
    if (wg == 1) return;

#pragma unroll
    for (int i = 0; i < NACC; i++)
        acc[i] += smem[i * 128 + lid];

    const int y = tY + ty;
    const int xb = tX + txg * 4;
    const int px = y * 96 + xb;
#pragma unroll
    for (int cg = 0; cg < COPB / 4; cg++) {
#pragma unroll
        for (int co4 = 0; co4 < 4; co4++) {
            const int co = cg * 4 + co4;
            const float b = bias[coBase + co];
            float4 v;
            v.x = acc[cg * 16 + co4 * 4 + 0] + b;
            v.y = acc[cg * 16 + co4 * 4 + 1] + b;
            v.z = acc[cg * 16 + co4 * 4 + 2] + b;
            v.w = acc[cg * 16 + co4 * 4 + 3] + b;
            if (act) {
                v.x = (v.x >= 0.f) ? v.x : 0.1f * v.x;
                v.y = (v.y >= 0.f) ? v.y : 0.1f * v.y;
                v.z = (v.z >= 0.f) ? v.z : 0.1f * v.z;
                v.w = (v.w >= 0.f) ? v.w : 0.1f * v.w;
            }
            const int o = (coBase + co) * HWP + px;
            if (addsrc) {
                float4 a = *(const float4*)(addsrc + o);
                v.x += a.x; v.y += a.y; v.z += a.z; v.w += a.w;
            }
            *(float4*)(out + o) = v;
        }
    }
}

#define CONV_SMEM4 (NSTG * (SW_OFF + 288) * 4)   // 72576 B
#define CONV_SMEM8 (NSTG * (SW_OFF + 576) * 4)   // 76032 B

// ---------------------------------------------------------------------------
// Modulated deformable sampling. grid = (72, 144) = (pix/128, dg*K).
// ---------------------------------------------------------------------------
__global__ __launch_bounds__(128) void dcn_sample_k(
    const float* __restrict__ xin0, const float* __restrict__ xin1,
    const float* __restrict__ out4, float* __restrict__ cols)
{
    const int pix = blockIdx.x * 128 + threadIdx.x;
    const int gk = blockIdx.y;
    const int g = gk / 9, k = gk - g * 9;
    const int h = pix / 96, w = pix - h * 96;

    const float offY = 5.f * tanhf(out4[(gk * 2 + 0) * HWP + pix]);
    const float offX = 5.f * tanhf(out4[(gk * 2 + 1) * HWP + pix]);
    const float mraw = out4[(288 + gk) * HWP + pix];
    const float m = 1.f / (1.f + expf(-mraw));

    const int ky = k / 3, kx = k - ky * 3;
    const float sy = offY + (float)(h - 1 + ky);
    const float sx = offX + (float)(w - 1 + kx);
    const float y0f = floorf(sy), x0f = floorf(sx);
    const float fy = sy - y0f, fx = sx - x0f;
    const int y0 = (int)y0f, x0 = (int)x0f;

    const bool vy0 = (y0 >= 0) && (y0 < 96);
    const bool vy1 = (y0 + 1 >= 0) && (y0 + 1 < 96);
    const bool vx0 = (x0 >= 0) && (x0 < 96);
    const bool vx1 = (x0 + 1 >= 0) && (x0 + 1 < 96);
    const int cy0 = min(max(y0, 0), 95), cy1 = min(max(y0 + 1, 0), 95);
    const int cx0 = min(max(x0, 0), 95), cx1 = min(max(x0 + 1, 0), 95);

    const float w00 = (1.f - fy) * (1.f - fx) * ((vy0 && vx0) ? 1.f : 0.f);
    const float w01 = (1.f - fy) * fx         * ((vy0 && vx1) ? 1.f : 0.f);
    const float w10 = fy * (1.f - fx)         * ((vy1 && vx0) ? 1.f : 0.f);
    const float w11 = fy * fx                 * ((vy1 && vx1) ? 1.f : 0.f);

    const int i00 = cy0 * 96 + cx0, i01 = cy0 * 96 + cx1;
    const int i10 = cy1 * 96 + cx0, i11 = cy1 * 96 + cx1;

#pragma unroll
    for (int c = 0; c < 8; c++) {
        const int cin = g * 8 + c;
        const float* p = (cin < 64) ? xin0 : xin1;
        float v = 0.f;
        if (p) {
            const float* pc = p + (cin & 63) * HWP;
            v = w00 * pc[i00] + w01 * pc[i01] + w10 * pc[i10] + w11 * pc[i11];
        }
        cols[(cin * 9 + k) * HWP + pix] = v * m;
    }
}

// ---------------------------------------------------------------------------
// GEMM: out[64,HWP] = W[64,K] @ in[K,HWP] + bias (+add). grid = (36, 8).
// Weights staged ONCE in smem as duplicated (w,w) pairs -> no in-loop
// barriers; FFMA2 over the natural (px0,px1) pair from LDG.64.
// Dynamic smem = K*16*4 bytes.
// ---------------------------------------------------------------------------
__global__ __launch_bounds__(128) void gemm_k(
    const float* __restrict__ in0, const float* __restrict__ in1,
    int ksplit, int K,
    const float* __restrict__ wgt, const float* __restrict__ bias,
    const float* __restrict__ addsrc, float* __restrict__ out)
{
    extern __shared__ float sw[];     // [co][k][2] duplicated weights
    const int tid = threadIdx.x;
    const int pix0 = blockIdx.x * 256 + tid * 2;
    const int coBase = blockIdx.y * 8;

    // one-time duplicated weight staging (coalesced LDG, conflict-free STS.64)
#pragma unroll
    for (int co = 0; co < 8; co++) {
        const float* wr = wgt + (coBase + co) * K;
        float2* dst = (float2*)(sw + co * K * 2);
        for (int j = tid; j < K; j += 128) {
            const float w = wr[j];
            dst[j] = make_float2(w, w);
        }
    }
    __syncthreads();

    u64 acc2[8];
#pragma unroll
    for (int i = 0; i < 8; i++) acc2[i] = pk(0.f, 0.f);

    for (int k = 0; k < K; k += 2) {
        const float* p0 = (k < ksplit) ? (in0 + k * HWP)
                                       : (in1 + (k - ksplit) * HWP);
        const float* p1 = (k + 1 < ksplit) ? (in0 + (k + 1) * HWP)
                                           : (in1 + (k + 1 - ksplit) * HWP);
        const float2 va = *(const float2*)(p0 + pix0);
        const float2 vb = *(const float2*)(p1 + pix0);
        const u64 wa = pk(va.x, va.y);
        const u64 wb = pk(vb.x, vb.y);
#pragma unroll
        for (int co = 0; co < 8; co++) {
            const ulonglong2 ww = *(const ulonglong2*)(sw + co * K * 2 + k * 2);
            acc2[co] = ffma2(wa, ww.x, acc2[co]);
            acc2[co] = ffma2(wb, ww.y, acc2[co]);
        }
    }

#pragma unroll
    for (int co = 0; co < 8; co++) {
        const float b = bias[coBase + co];
        float2 v; upk(acc2[co], v.x, v.y);
        v.x += b; v.y += b;
        const int o = (coBase + co) * HWP + pix0;
        if (addsrc) {
            float2 a = *(const float2*)(addsrc + o);
            v.x += a.x; v.y += a.y;
        }
        *(float2*)(out + o) = v;
    }
}

#define GEMM_SMEM_BIG (1152 * 16 * 4)   // 73728 B
#define GEMM_SMEM_FUS (128 * 16 * 4)    // 8192 B

// ---------------------------------------------------------------------------
// Host orchestration
// ---------------------------------------------------------------------------
extern "C" void kernel_launch(void* const* d_in, const int* in_sizes, int n_in,
                              void* d_out, int out_size)
{
    (void)in_sizes; (void)n_in; (void)out_size;

    cudaFuncSetAttribute(conv3x3_k<4>, cudaFuncAttributeMaxDynamicSharedMemorySize,
                         CONV_SMEM4);
    cudaFuncSetAttribute(conv3x3_k<8>, cudaFuncAttributeMaxDynamicSharedMemorySize,
                         CONV_SMEM8);
    cudaFuncSetAttribute(gemm_k, cudaFuncAttributeMaxDynamicSharedMemorySize,
                         GEMM_SMEM_BIG);

    const float* x = (const float*)d_in[0];
    const float* P[2][14];
    for (int j = 0; j < 14; j++) {
        P[0][j] = (const float*)d_in[1 + j];
        P[1][j] = (const float*)d_in[15 + j];
    }
    const float* fus_w = (const float*)d_in[29];
    const float* fus_b = (const float*)d_in[30];
    float* out = (float*)d_out;

    float *fb, *ff, *hA, *hB, *o4, *cols, *dcn;
    cudaGetSymbolAddress((void**)&fb,  g_fb);
    cudaGetSymbolAddress((void**)&ff,  g_ff);
    cudaGetSymbolAddress((void**)&hA,  g_hA);
    cudaGetSymbolAddress((void**)&hB,  g_hB);
    cudaGetSymbolAddress((void**)&o4,  g_out4);
    cudaGetSymbolAddress((void**)&cols, g_cols);
    cudaGetSymbolAddress((void**)&dcn, g_dcn);

    const dim3 gc64(18, 16);    // conv<4>, Cout=64
    const dim3 gc432(18, 54);   // conv<8>, Cout=432
    const dim3 gg64(36, 8);

    for (int br = 0; br < 2; br++) {
        const float* const* p = P[br];
        float* F = (br == 0) ? fb : ff;
        const float* prop = nullptr;

        for (int i = 0; i < 8; i++) {
            const int fr = (br == 0) ? (7 - i) : i;
            const float* cur = x + fr * CH;
            const float* n2 = nullptr;
            if (i > 1) {
                int fr2 = (br == 0) ? (7 - (i - 2)) : (i - 2);
                n2 = F + fr2 * CH;
            }

            if (i > 0) {
                conv3x3_k<4><<<gc64, 256, CONV_SMEM4>>>(prop, cur, n2, 3, p[2], p[3], nullptr, hA, 1);
                conv3x3_k<4><<<gc64, 256, CONV_SMEM4>>>(hA, nullptr, nullptr, 1, p[4], p[5], nullptr, hB, 1);
                conv3x3_k<4><<<gc64, 256, CONV_SMEM4>>>(hB, nullptr, nullptr, 1, p[6], p[7], nullptr, hA, 1);
                conv3x3_k<8><<<gc432, 256, CONV_SMEM8>>>(hA, nullptr, nullptr, 1, p[8], p[9], nullptr, o4, 0);
                dcn_sample_k<<<dim3(72, 144), 128>>>(prop, n2, o4, cols);
                gemm_k<<<gg64, 128, GEMM_SMEM_BIG>>>(cols, cols, 1152, 1152, p[0], p[1], nullptr, dcn);
                prop = dcn;
            }

            if (br == 0)
                conv3x3_k<4><<<gc64, 256, CONV_SMEM4>>>(cur, prop, nullptr, 2, p[10], p[11], nullptr, hA, 1);
            else
                conv3x3_k<4><<<gc64, 256, CONV_SMEM4>>>(cur, fb + fr * CH, prop, 3, p[10], p[11], nullptr, hA, 1);
            conv3x3_k<4><<<gc64, 256, CONV_SMEM4>>>(hA, nullptr, nullptr, 1, p[12], p[13], prop, F + fr * CH, 0);
            prop = F + fr * CH;
        }
    }

    for (int f = 0; f < 8; f++) {
        gemm_k<<<gg64, 128, GEMM_SMEM_FUS>>>(fb + f * CH, ff + f * CH, 64, 128,
                                             fus_w, fus_b, x + f * CH, out + f * CH);
    }
}

// round 12
// speedup vs baseline: 1.3042x; 1.3042x over previous
#include <cuda_runtime.h>
#include <math.h>
#include <stdint.h>

// ----------------------------------------------------------------------------
// BidirectionalPropagation (BasicVSR++ style) on GB300. B=1,T=8,C=64,96x96,DG=16
// R11: gemm reverted to R8 (FFMA2 abandoned — two measured regressions).
//      conv3x3: ROWW 40 -> 48 so edge-scalar LDS drop from 4-way to 2-way
//      bank conflicts (input wavefronts/cin 36 -> 24). Staging slot count
//      unchanged; per-slot smem offsets precomputed.
// ----------------------------------------------------------------------------

#define HWP 9216          // 96*96
#define CH  (64 * HWP)

__device__ float g_fb[8][CH];
__device__ float g_ff[8][CH];
__device__ float g_hA[CH];
__device__ float g_hB[CH];
__device__ float g_out4[432 * HWP];
__device__ float g_cols[1152 * HWP];
__device__ float g_dcn[CH];

#define ROWW   48
#define CINSZ  (18 * ROWW)          // 864 floats per cin (40 data + 8 pad cols)
#define SW_OFF (8 * CINSZ)          // 6912
#define NSTG   3

__device__ __forceinline__ void cp16(uint32_t d, const void* g, int sz) {
    asm volatile("cp.async.ca.shared.global [%0], [%1], 16, %2;\n"
                 :: "r"(d), "l"(g), "r"(sz));
}
__device__ __forceinline__ void cp4(uint32_t d, const void* g) {
    asm volatile("cp.async.ca.shared.global [%0], [%1], 4;\n"
                 :: "r"(d), "l"(g));
}
#define CP_COMMIT() asm volatile("cp.async.commit_group;\n" ::: "memory")
#define CP_WAIT1()  asm volatile("cp.async.wait_group 1;\n" ::: "memory")

// ---------------------------------------------------------------------------
// conv3x3: tile 32x16 px, 256 threads, cin-split across two warp-groups.
// Each thread: 4 consecutive px x COPB couts. grid = (18, Cout/COPB).
// ---------------------------------------------------------------------------
template <int COPB>
__global__ __launch_bounds__(256) void conv3x3_k(
    const float* __restrict__ in0, const float* __restrict__ in1,
    const float* __restrict__ in2, int cinBlocks,
    const float* __restrict__ wgt, const float* __restrict__ bias,
    const float* __restrict__ addsrc, float* __restrict__ out, int act)
{
    constexpr int WSLOTS = 8 * 9 * COPB;
    constexpr int STG_F  = SW_OFF + WSLOTS;
    constexpr int NWIT   = (WSLOTS + 255) / 256;
    constexpr int NACC   = 4 * COPB;

    extern __shared__ float smem[];
    const int tid = threadIdx.x;
    const int tX = (blockIdx.x % 3) * 32;
    const int tY = (blockIdx.x / 3) * 16;
    const int coBase = blockIdx.y * COPB;
    const int lid  = tid & 127;
    const int wg   = tid >> 7;
    const int txg  = lid & 7;
    const int ty   = lid >> 3;
    const int Cin = cinBlocks * 64;

    const float* ptrs[3] = {in0, in1, in2};
    const float* actp[3]; int actc[3]; int na = 0;
    for (int b = 0; b < cinBlocks; b++)
        if (ptrs[b]) { actp[na] = ptrs[b]; actc[na] = b * 64; na++; }
    const int nSuper = na * 8;

    // ---- precompute staging tuples (256 threads) ----
    // 1440 float4 slots; slot = c*180 + r*10 + q -> smem (c*864 + r*48 + q*4)
    int in_goff[6]; uint32_t in_soff[6]; unsigned in_val = 0;
#pragma unroll
    for (int i = 0; i < 6; i++) {
        int slot = tid + i * 256;
        if (slot < 1440) {
            int c = slot / 180; int rem = slot - c * 180;
            int r = rem / 10;   int q = rem - r * 10;
            int gy = tY - 1 + r, gx = tX - 4 + q * 4;
            bool v = ((unsigned)gy < 96u) && ((unsigned)gx < 96u);
            in_goff[i] = v ? (c * HWP + gy * 96 + gx) : 0;
            in_soff[i] = (uint32_t)(c * CINSZ + r * ROWW + q * 4) * 4u;
            if (v) in_val |= (1u << i);
        } else { in_goff[i] = 0; in_soff[i] = 0; }
    }
    int w_goff[NWIT];
#pragma unroll
    for (int i = 0; i < NWIT; i++) {
        int slot = tid + i * 256;
        if (slot < WSLOTS) {
            int c = slot / (9 * COPB); int rem = slot - c * (9 * COPB);
            int k9 = rem / COPB;       int co = rem - k9 * COPB;
            w_goff[i] = ((coBase + co) * Cin + c) * 9 + k9;
        } else w_goff[i] = 0;
    }

    const uint32_t s32 = (uint32_t)__cvta_generic_to_shared(smem);

    auto PREFETCH = [&](int sb, int stg) {
        const float* base = actp[sb >> 3] + ((sb & 7) * 8) * HWP;
        const uint32_t d0 = s32 + (uint32_t)stg * (STG_F * 4);
#pragma unroll
        for (int i = 0; i < 5; i++)
            cp16(d0 + in_soff[i], base + in_goff[i], ((in_val >> i) & 1) ? 16 : 0);
        if (tid < 160)
            cp16(d0 + in_soff[5], base + in_goff[5], ((in_val >> 5) & 1) ? 16 : 0);
        const float* wbase = wgt + (actc[sb >> 3] + (sb & 7) * 8) * 9;
        const uint32_t w0 = s32 + (uint32_t)stg * (STG_F * 4) + SW_OFF * 4 + tid * 4;
#pragma unroll
        for (int i = 0; i < NWIT; i++) {
            if (tid + i * 256 < WSLOTS)
                cp4(w0 + i * 1024, wbase + w_goff[i]);
        }
    };

    float acc[NACC];
#pragma unroll
    for (int i = 0; i < NACC; i++) acc[i] = 0.f;

    PREFETCH(0, 0); CP_COMMIT();
    PREFETCH(1, 1); CP_COMMIT();

    int stg = 0, pstg = 2;
    for (int s = 0; s < nSuper; s++) {
        CP_WAIT1();
        __syncthreads();
        const float* st = smem + stg * STG_F;

#pragma unroll
        for (int cc8 = 0; cc8 < 4; cc8++) {
            const int c = wg * 4 + cc8;
            const float* sp = st + c * CINSZ + ty * ROWW + txg * 4;
            float iv[18];
#pragma unroll
            for (int r = 0; r < 3; r++) {
                const float4 m = *(const float4*)(sp + r * ROWW + 4);
                iv[r * 6 + 0] = sp[r * ROWW + 3];
                iv[r * 6 + 1] = m.x; iv[r * 6 + 2] = m.y;
                iv[r * 6 + 3] = m.z; iv[r * 6 + 4] = m.w;
                iv[r * 6 + 5] = sp[r * ROWW + 8];
            }
            const float* wp = st + SW_OFF + c * (9 * COPB);
#pragma unroll
            for (int k9 = 0; k9 < 9; k9++) {
                const int r = k9 / 3, ccc = k9 - r * 3;
#pragma unroll
                for (int cg = 0; cg < COPB / 4; cg++) {
                    const float4 wv = *(const float4*)(wp + k9 * COPB + cg * 4);
#pragma unroll
                    for (int j = 0; j < 4; j++) {
                        const float x = iv[r * 6 + ccc + j];
                        acc[cg * 16 + 0  + j] = fmaf(x, wv.x, acc[cg * 16 + 0  + j]);
                        acc[cg * 16 + 4  + j] = fmaf(x, wv.y, acc[cg * 16 + 4  + j]);
                        acc[cg * 16 + 8  + j] = fmaf(x, wv.z, acc[cg * 16 + 8  + j]);
                        acc[cg * 16 + 12 + j] = fmaf(x, wv.w, acc[cg * 16 + 12 + j]);
                    }
                }
            }
        }

        if (s + 2 < nSuper) PREFETCH(s + 2, pstg);
        CP_COMMIT();
        stg = (stg == 2) ? 0 : stg + 1;
        pstg = (pstg == 2) ? 0 : pstg + 1;
    }

    // ---- merge the two cin halves (reuse stage smem; pipeline drained) ----
    __syncthreads();
    if (wg == 1) {
#pragma unroll
        for (int i = 0; i < NACC; i++)
            smem[i * 128 + lid] = acc[i];
    }
    __syncthreads();
    if (wg == 1) return;

#pragma unroll
    for (int i = 0; i < NACC; i++)
        acc[i] += smem[i * 128 + lid];

    const int y = tY + ty;
    const int xb = tX + txg * 4;
    const int px = y * 96 + xb;
#pragma unroll
    for (int cg = 0; cg < COPB / 4; cg++) {
#pragma unroll
        for (int co4 = 0; co4 < 4; co4++) {
            const int co = cg * 4 + co4;
            const float b = bias[coBase + co];
            float4 v;
            v.x = acc[cg * 16 + co4 * 4 + 0] + b;
            v.y = acc[cg * 16 + co4 * 4 + 1] + b;
            v.z = acc[cg * 16 + co4 * 4 + 2] + b;
            v.w = acc[cg * 16 + co4 * 4 + 3] + b;
            if (act) {
                v.x = (v.x >= 0.f) ? v.x : 0.1f * v.x;
                v.y = (v.y >= 0.f) ? v.y : 0.1f * v.y;
                v.z = (v.z >= 0.f) ? v.z : 0.1f * v.z;
                v.w = (v.w >= 0.f) ? v.w : 0.1f * v.w;
            }
            const int o = (coBase + co) * HWP + px;
            if (addsrc) {
                float4 a = *(const float4*)(addsrc + o);
                v.x += a.x; v.y += a.y; v.z += a.z; v.w += a.w;
            }
            *(float4*)(out + o) = v;
        }
    }
}

#define CONV_SMEM4 (NSTG * (SW_OFF + 288) * 4)   // 86400 B
#define CONV_SMEM8 (NSTG * (SW_OFF + 576) * 4)   // 89856 B

// ---------------------------------------------------------------------------
// Modulated deformable sampling. grid = (72, 144) = (pix/128, dg*K).
// ---------------------------------------------------------------------------
__global__ __launch_bounds__(128) void dcn_sample_k(
    const float* __restrict__ xin0, const float* __restrict__ xin1,
    const float* __restrict__ out4, float* __restrict__ cols)
{
    const int pix = blockIdx.x * 128 + threadIdx.x;
    const int gk = blockIdx.y;
    const int g = gk / 9, k = gk - g * 9;
    const int h = pix / 96, w = pix - h * 96;

    const float offY = 5.f * tanhf(out4[(gk * 2 + 0) * HWP + pix]);
    const float offX = 5.f * tanhf(out4[(gk * 2 + 1) * HWP + pix]);
    const float mraw = out4[(288 + gk) * HWP + pix];
    const float m = 1.f / (1.f + expf(-mraw));

    const int ky = k / 3, kx = k - ky * 3;
    const float sy = offY + (float)(h - 1 + ky);
    const float sx = offX + (float)(w - 1 + kx);
    const float y0f = floorf(sy), x0f = floorf(sx);
    const float fy = sy - y0f, fx = sx - x0f;
    const int y0 = (int)y0f, x0 = (int)x0f;

    const bool vy0 = (y0 >= 0) && (y0 < 96);
    const bool vy1 = (y0 + 1 >= 0) && (y0 + 1 < 96);
    const bool vx0 = (x0 >= 0) && (x0 < 96);
    const bool vx1 = (x0 + 1 >= 0) && (x0 + 1 < 96);
    const int cy0 = min(max(y0, 0), 95), cy1 = min(max(y0 + 1, 0), 95);
    const int cx0 = min(max(x0, 0), 95), cx1 = min(max(x0 + 1, 0), 95);

    const float w00 = (1.f - fy) * (1.f - fx) * ((vy0 && vx0) ? 1.f : 0.f);
    const float w01 = (1.f - fy) * fx         * ((vy0 && vx1) ? 1.f : 0.f);
    const float w10 = fy * (1.f - fx)         * ((vy1 && vx0) ? 1.f : 0.f);
    const float w11 = fy * fx                 * ((vy1 && vx1) ? 1.f : 0.f);

    const int i00 = cy0 * 96 + cx0, i01 = cy0 * 96 + cx1;
    const int i10 = cy1 * 96 + cx0, i11 = cy1 * 96 + cx1;

#pragma unroll
    for (int c = 0; c < 8; c++) {
        const int cin = g * 8 + c;
        const float* p = (cin < 64) ? xin0 : xin1;
        float v = 0.f;
        if (p) {
            const float* pc = p + (cin & 63) * HWP;
            v = w00 * pc[i00] + w01 * pc[i01] + w10 * pc[i10] + w11 * pc[i11];
        }
        cols[(cin * 9 + k) * HWP + pix] = v * m;
    }
}

// ---------------------------------------------------------------------------
// GEMM (R8): out[64,HWP] = W[64,K] @ in[K,HWP] + bias (+add). grid = (36, 8).
// ---------------------------------------------------------------------------
__global__ __launch_bounds__(128) void gemm_k(
    const float* __restrict__ in0, const float* __restrict__ in1,
    int ksplit, int K,
    const float* __restrict__ wgt, const float* __restrict__ bias,
    const float* __restrict__ addsrc, float* __restrict__ out)
{
    __shared__ float s_w[8][8];
    const int tid = threadIdx.x;
    const int pix0 = blockIdx.x * 256 + tid * 2;
    const int coBase = blockIdx.y * 8;

    float acc0[8], acc1[8];
#pragma unroll
    for (int i = 0; i < 8; i++) { acc0[i] = 0.f; acc1[i] = 0.f; }

    for (int k0 = 0; k0 < K; k0 += 8) {
        __syncthreads();
        if (tid < 64)
            s_w[tid >> 3][tid & 7] = wgt[(coBase + (tid & 7)) * K + k0 + (tid >> 3)];
        __syncthreads();
#pragma unroll
        for (int kk = 0; kk < 8; kk++) {
            const int k = k0 + kk;
            const float* p = (k < ksplit) ? (in0 + k * HWP)
                                          : (in1 + (k - ksplit) * HWP);
            const float2 v = *(const float2*)(p + pix0);
#pragma unroll
            for (int co = 0; co < 8; co++) {
                acc0[co] = fmaf(v.x, s_w[kk][co], acc0[co]);
                acc1[co] = fmaf(v.y, s_w[kk][co], acc1[co]);
            }
        }
    }

#pragma unroll
    for (int co = 0; co < 8; co++) {
        const float b = bias[coBase + co];
        float2 v; v.x = acc0[co] + b; v.y = acc1[co] + b;
        const int o = (coBase + co) * HWP + pix0;
        if (addsrc) {
            float2 a = *(const float2*)(addsrc + o);
            v.x += a.x; v.y += a.y;
        }
        *(float2*)(out + o) = v;
    }
}

// ---------------------------------------------------------------------------
// Host orchestration
// ---------------------------------------------------------------------------
extern "C" void kernel_launch(void* const* d_in, const int* in_sizes, int n_in,
                              void* d_out, int out_size)
{
    (void)in_sizes; (void)n_in; (void)out_size;

    cudaFuncSetAttribute(conv3x3_k<4>, cudaFuncAttributeMaxDynamicSharedMemorySize,
                         CONV_SMEM4);
    cudaFuncSetAttribute(conv3x3_k<8>, cudaFuncAttributeMaxDynamicSharedMemorySize,
                         CONV_SMEM8);

    const float* x = (const float*)d_in[0];
    const float* P[2][14];
    for (int j = 0; j < 14; j++) {
        P[0][j] = (const float*)d_in[1 + j];
        P[1][j] = (const float*)d_in[15 + j];
    }
    const float* fus_w = (const float*)d_in[29];
    const float* fus_b = (const float*)d_in[30];
    float* out = (float*)d_out;

    float *fb, *ff, *hA, *hB, *o4, *cols, *dcn;
    cudaGetSymbolAddress((void**)&fb,  g_fb);
    cudaGetSymbolAddress((void**)&ff,  g_ff);
    cudaGetSymbolAddress((void**)&hA,  g_hA);
    cudaGetSymbolAddress((void**)&hB,  g_hB);
    cudaGetSymbolAddress((void**)&o4,  g_out4);
    cudaGetSymbolAddress((void**)&cols, g_cols);
    cudaGetSymbolAddress((void**)&dcn, g_dcn);

    const dim3 gc64(18, 16);    // conv<4>, Cout=64
    const dim3 gc432(18, 54);   // conv<8>, Cout=432
    const dim3 gg64(36, 8);

    for (int br = 0; br < 2; br++) {
        const float* const* p = P[br];
        float* F = (br == 0) ? fb : ff;
        const float* prop = nullptr;

        for (int i = 0; i < 8; i++) {
            const int fr = (br == 0) ? (7 - i) : i;
            const float* cur = x + fr * CH;
            const float* n2 = nullptr;
            if (i > 1) {
                int fr2 = (br == 0) ? (7 - (i - 2)) : (i - 2);
                n2 = F + fr2 * CH;
            }

            if (i > 0) {
                conv3x3_k<4><<<gc64, 256, CONV_SMEM4>>>(prop, cur, n2, 3, p[2], p[3], nullptr, hA, 1);
                conv3x3_k<4><<<gc64, 256, CONV_SMEM4>>>(hA, nullptr, nullptr, 1, p[4], p[5], nullptr, hB, 1);
                conv3x3_k<4><<<gc64, 256, CONV_SMEM4>>>(hB, nullptr, nullptr, 1, p[6], p[7], nullptr, hA, 1);
                conv3x3_k<8><<<gc432, 256, CONV_SMEM8>>>(hA, nullptr, nullptr, 1, p[8], p[9], nullptr, o4, 0);
                dcn_sample_k<<<dim3(72, 144), 128>>>(prop, n2, o4, cols);
                gemm_k<<<gg64, 128>>>(cols, cols, 1152, 1152, p[0], p[1], nullptr, dcn);
                prop = dcn;
            }

            if (br == 0)
                conv3x3_k<4><<<gc64, 256, CONV_SMEM4>>>(cur, prop, nullptr, 2, p[10], p[11], nullptr, hA, 1);
            else
                conv3x3_k<4><<<gc64, 256, CONV_SMEM4>>>(cur, fb + fr * CH, prop, 3, p[10], p[11], nullptr, hA, 1);
            conv3x3_k<4><<<gc64, 256, CONV_SMEM4>>>(hA, nullptr, nullptr, 1, p[12], p[13], prop, F + fr * CH, 0);
            prop = F + fr * CH;
        }
    }

    for (int f = 0; f < 8; f++) {
        gemm_k<<<gg64, 128>>>(fb + f * CH, ff + f * CH, 64, 128,
                              fus_w, fus_b, x + f * CH, out + f * CH);
    }
}